// round 11
// baseline (speedup 1.0000x reference)
#include <cuda_runtime.h>
#include <cuda_fp16.h>
#include <cstdint>
#include <cstddef>

// Problem constants
#define B_    8192
#define D_    1024
#define H_    2048
#define O_    1024
#define T_    4
#define NOPS_ 3

// GEMM tiling (fp16, m16n8k16): block 128x256, 8 warps, warp tile 64x64
#define BM 128
#define BN 256
#define BK 64                    // halves; 128B row
#define LDH 72                   // BK + 8 pad -> conflict-free ldmatrix
#define STAGES 3
#define NTHREADS 256
#define SMEM_BYTES (STAGES * (BM * LDH + BN * LDH) * 2)   // 165888; 1 CTA/SM

// ---------------- scratch (static device memory, allowed) ----------------
__device__ __half g_xh  [(size_t)B_ * D_];                  // fp16 x
__device__ __half g_Wph [(size_t)T_ * H_ * D_];             // fp16 Wp
__device__ __half g_Woph[(size_t)T_ * NOPS_ * H_ * H_];     // fp16 Wop (routed experts only)
__device__ __half g_Wrh [(size_t)O_ * T_ * H_];             // fp16 Wr
__device__ __half g_xp  [(size_t)T_ * B_ * H_];             // stage-1 out
__device__ __half g_h   [(size_t)T_ * B_ * H_];             // stage-2 out
__device__ __half g_cat [(size_t)B_ * T_ * H_];             // stage-3 out, [B, T*H]
__device__ int    g_idx [T_ * 2];

// ---------------- routing: top-2 of logits per temper ----------------
__global__ void route_kernel(const float* __restrict__ logits) {
    int t = threadIdx.x;
    if (t < T_) {
        const float* l = logits + t * NOPS_;
        int i0 = 0;
        #pragma unroll
        for (int i = 1; i < NOPS_; i++) if (l[i] > l[i0]) i0 = i;
        int i1 = -1;
        #pragma unroll
        for (int i = 0; i < NOPS_; i++) {
            if (i == i0) continue;
            if (i1 < 0 || l[i] > l[i1]) i1 = i;
        }
        g_idx[t * 2 + 0] = i0;
        g_idx[t * 2 + 1] = i1;
    }
}

// ---------------- fp32 -> fp16 conversion ----------------
__global__ void cvt_half(const float4* __restrict__ src, __half* __restrict__ dst, int n4) {
    int i = blockIdx.x * blockDim.x + threadIdx.x;
    if (i < n4) {
        float4 v = src[i];
        __half2 h01 = __floats2half2_rn(v.x, v.y);
        __half2 h23 = __floats2half2_rn(v.z, v.w);
        uint2 u;
        u.x = *reinterpret_cast<uint32_t*>(&h01);
        u.y = *reinterpret_cast<uint32_t*>(&h23);
        reinterpret_cast<uint2*>(dst)[i] = u;
    }
}

// convert only the experts routing selected (z = t*NOPS+op)
__global__ void cvt_half_gated(const float4* __restrict__ src, __half* __restrict__ dst, int n4_per_z) {
    int z = blockIdx.y;
    int t = z / NOPS_, op = z % NOPS_;
    if (g_idx[t * 2] != op && g_idx[t * 2 + 1] != op) return;
    int i = blockIdx.x * blockDim.x + threadIdx.x;
    if (i < n4_per_z) {
        size_t off = (size_t)z * n4_per_z + i;
        float4 v = src[off];
        __half2 h01 = __floats2half2_rn(v.x, v.y);
        __half2 h23 = __floats2half2_rn(v.z, v.w);
        uint2 u;
        u.x = *reinterpret_cast<uint32_t*>(&h01);
        u.y = *reinterpret_cast<uint32_t*>(&h23);
        reinterpret_cast<uint2*>(dst)[off] = u;
    }
}

// ---------------- mma / ldmatrix ----------------
__device__ __forceinline__ void mma_f16(float* c, const uint32_t* a, const uint32_t* b) {
    asm volatile(
        "mma.sync.aligned.m16n8k16.row.col.f32.f16.f16.f32 "
        "{%0,%1,%2,%3}, {%4,%5,%6,%7}, {%8,%9}, {%0,%1,%2,%3};"
        : "+f"(c[0]), "+f"(c[1]), "+f"(c[2]), "+f"(c[3])
        : "r"(a[0]), "r"(a[1]), "r"(a[2]), "r"(a[3]),
          "r"(b[0]), "r"(b[1]));
}

__device__ __forceinline__ void ldsm_x4(uint32_t& r0, uint32_t& r1, uint32_t& r2, uint32_t& r3,
                                        uint32_t addr) {
    asm volatile("ldmatrix.sync.aligned.m8n8.x4.shared.b16 {%0,%1,%2,%3}, [%4];"
                 : "=r"(r0), "=r"(r1), "=r"(r2), "=r"(r3) : "r"(addr));
}

#define CP_ASYNC16(smem_u32, gptr) \
    asm volatile("cp.async.cg.shared.global [%0], [%1], 16;\n" :: "r"(smem_u32), "l"(gptr))
#define CP_COMMIT() asm volatile("cp.async.commit_group;\n" ::)
#define CP_WAIT(n)  asm volatile("cp.async.wait_group %0;\n" :: "n"(n))

// ---------------- fused fp16 GEMM: C = act(A @ W^T + bias) ----------------
__global__ void __launch_bounds__(NTHREADS, 1)
gemm_f16(const __half* __restrict__ Abase, size_t strideAz, int lda,
         const __half* __restrict__ Wbase, size_t strideWz,
         const float* __restrict__ biasBase, size_t strideBz,
         void* __restrict__ Cbase, size_t strideCz, int ldc,
         int K,
         const int* __restrict__ idxbuf, int which,
         size_t selStrideW, size_t selStrideB,
         int do_relu, int out_half)
{
    extern __shared__ __half smem[];
    __half* As = smem;                           // [STAGES][BM][LDH]
    __half* Ws = smem + STAGES * BM * LDH;       // [STAGES][BN][LDH]

    const int z = blockIdx.z;
    const __half* A    = Abase + (size_t)z * strideAz;
    const __half* W    = Wbase + (size_t)z * strideWz;
    const float*  bias = biasBase + (size_t)z * strideBz;
    if (idxbuf) {
        int sel = idxbuf[z * 2 + which];
        W    += (size_t)sel * selStrideW;
        bias += (size_t)sel * selStrideB;
    }

    const int bm = blockIdx.y * BM;
    const int bn = blockIdx.x * BN;

    const int tid  = threadIdx.x;
    const int wid  = tid >> 5;
    const int lane = tid & 31;
    const int gid  = lane >> 2;
    const int tig  = lane & 3;

    // warp grid: 2 (M) x 4 (N); warp tile 64 x 64
    const int wm = (wid & 1) * 64;
    const int wn = (wid >> 1) * 64;

    // cp.async mapping: 32 rows x 8 chunks (16B) per pass
    const int lr = tid >> 3;          // 0..31
    const int lc = (tid & 7) * 8;     // halves

    uint32_t As_u = (uint32_t)__cvta_generic_to_shared(As);
    uint32_t Ws_u = (uint32_t)__cvta_generic_to_shared(Ws);

    // ldmatrix per-lane base addresses (bytes), stage 0, k-step 0
    // A x4: lanes 0-7 rows 0-7 k0 | 8-15 rows 8-15 k0 | 16-23 rows 0-7 k+8 | 24-31 rows 8-15 k+8
    const int a_row  = wm + (lane & 15);
    const int a_koff = (lane >> 4) * 8;
    uint32_t lmA0 = As_u + (uint32_t)((a_row * LDH + a_koff) * 2);
    // B x4: lanes 0-7 n+0..7 k0 | 8-15 n+0..7 k+8 | 16-23 n+8..15 k0 | 24-31 n+8..15 k+8
    const int b_row  = wn + ((lane >> 4) << 3) + (lane & 7);
    const int b_koff = ((lane >> 3) & 1) * 8;
    uint32_t lmB0 = Ws_u + (uint32_t)((b_row * LDH + b_koff) * 2);

    const int numK = K / BK;

    auto load_stage = [&](int stage, int k0) {
        #pragma unroll
        for (int i = 0; i < 4; i++) {           // A: 128 rows
            int r = lr + i * 32;
            const __half* srcA = A + (size_t)(bm + r) * lda + k0 + lc;
            uint32_t dstA = As_u + (uint32_t)(((stage * BM + r) * LDH + lc) * 2);
            CP_ASYNC16(dstA, srcA);
        }
        #pragma unroll
        for (int i = 0; i < 8; i++) {           // B: 256 rows
            int r = lr + i * 32;
            const __half* srcW = W + (size_t)(bn + r) * lda + k0 + lc;
            uint32_t dstW = Ws_u + (uint32_t)(((stage * BN + r) * LDH + lc) * 2);
            CP_ASYNC16(dstW, srcW);
        }
    };

    float acc[4][8][4];
    #pragma unroll
    for (int mi = 0; mi < 4; mi++)
        #pragma unroll
        for (int ni = 0; ni < 8; ni++)
            #pragma unroll
            for (int i = 0; i < 4; i++) acc[mi][ni][i] = 0.0f;

    load_stage(0, 0);
    CP_COMMIT();
    load_stage(1, BK);
    CP_COMMIT();

    for (int kt = 0; kt < numK; kt++) {
        if (kt + 1 < numK) { CP_WAIT(1); } else { CP_WAIT(0); }
        __syncthreads();

        const int nx = kt + 2;
        if (nx < numK) {
            load_stage(nx % STAGES, nx * BK);
            CP_COMMIT();
        }

        const int buf = kt % STAGES;
        const uint32_t stA = lmA0 + (uint32_t)(buf * BM * LDH * 2);
        const uint32_t stB = lmB0 + (uint32_t)(buf * BN * LDH * 2);

        #pragma unroll
        for (int kk = 0; kk < BK; kk += 16) {
            uint32_t af[4][4], bf[8][2];
            #pragma unroll
            for (int mi = 0; mi < 4; mi++)
                ldsm_x4(af[mi][0], af[mi][1], af[mi][2], af[mi][3],
                        stA + (uint32_t)((mi * 16 * LDH + kk) * 2));
            #pragma unroll
            for (int nb = 0; nb < 4; nb++)
                ldsm_x4(bf[2 * nb][0], bf[2 * nb][1], bf[2 * nb + 1][0], bf[2 * nb + 1][1],
                        stB + (uint32_t)((nb * 16 * LDH + kk) * 2));
            #pragma unroll
            for (int mi = 0; mi < 4; mi++)
                #pragma unroll
                for (int ni = 0; ni < 8; ni++)
                    mma_f16(acc[mi][ni], af[mi], bf[ni]);
        }
    }

    // epilogue: bias + optional relu; store fp16 (intermediate) or fp32 (final)
    #pragma unroll
    for (int mi = 0; mi < 4; mi++) {
        const int row0 = bm + wm + mi * 16 + gid;
        #pragma unroll
        for (int ni = 0; ni < 8; ni++) {
            const int col = bn + wn + ni * 8 + tig * 2;
            float b0 = bias[col];
            float b1 = bias[col + 1];
            float v0 = acc[mi][ni][0] + b0;
            float v1 = acc[mi][ni][1] + b1;
            float v2 = acc[mi][ni][2] + b0;
            float v3 = acc[mi][ni][3] + b1;
            if (do_relu) {
                v0 = fmaxf(v0, 0.0f); v1 = fmaxf(v1, 0.0f);
                v2 = fmaxf(v2, 0.0f); v3 = fmaxf(v3, 0.0f);
            }
            if (out_half) {
                __half* C = (__half*)Cbase + (size_t)z * strideCz;
                __half2 h0 = __floats2half2_rn(v0, v1);
                __half2 h1 = __floats2half2_rn(v2, v3);
                *reinterpret_cast<__half2*>(C + (size_t)row0 * ldc + col) = h0;
                *reinterpret_cast<__half2*>(C + (size_t)(row0 + 8) * ldc + col) = h1;
            } else {
                float* C = (float*)Cbase + (size_t)z * strideCz;
                *reinterpret_cast<float2*>(C + (size_t)row0 * ldc + col) = make_float2(v0, v1);
                *reinterpret_cast<float2*>(C + (size_t)(row0 + 8) * ldc + col) = make_float2(v2, v3);
            }
        }
    }
}

// ---------------- launch ----------------
extern "C" void kernel_launch(void* const* d_in, const int* in_sizes, int n_in,
                              void* d_out, int out_size)
{
    const float* x      = (const float*)d_in[0];
    const float* Wp     = (const float*)d_in[1];
    const float* bp     = (const float*)d_in[2];
    const float* Wop    = (const float*)d_in[3];
    const float* bop    = (const float*)d_in[4];
    const float* logits = (const float*)d_in[5];
    const float* Wr     = (const float*)d_in[6];
    const float* br     = (const float*)d_in[7];
    float* out = (float*)d_out;

    cudaFuncSetAttribute(gemm_f16, cudaFuncAttributeMaxDynamicSharedMemorySize, SMEM_BYTES);

    __half *xh, *Wph, *Woph, *Wrh, *xp_p, *h_p, *cat_p;
    int* idx_p;
    cudaGetSymbolAddress((void**)&xh,    g_xh);
    cudaGetSymbolAddress((void**)&Wph,   g_Wph);
    cudaGetSymbolAddress((void**)&Woph,  g_Woph);
    cudaGetSymbolAddress((void**)&Wrh,   g_Wrh);
    cudaGetSymbolAddress((void**)&xp_p,  g_xp);
    cudaGetSymbolAddress((void**)&h_p,   g_h);
    cudaGetSymbolAddress((void**)&cat_p, g_cat);
    cudaGetSymbolAddress((void**)&idx_p, g_idx);

    route_kernel<<<1, 32>>>(logits);

    // fp32 -> fp16 operand conversion
    {
        int n4;
        n4 = (B_ * D_) / 4;
        cvt_half<<<(n4 + 255) / 256, 256>>>((const float4*)x, xh, n4);
        n4 = (T_ * H_ * D_) / 4;
        cvt_half<<<(n4 + 255) / 256, 256>>>((const float4*)Wp, Wph, n4);
        n4 = (O_ * T_ * H_) / 4;
        cvt_half<<<(n4 + 255) / 256, 256>>>((const float4*)Wr, Wrh, n4);
        int n4z = (H_ * H_) / 4;
        dim3 g((n4z + 255) / 256, T_ * NOPS_);
        cvt_half_gated<<<g, 256>>>((const float4*)Wop, Woph, n4z);
    }

    dim3 blk(NTHREADS);
    dim3 g1(H_ / BN, B_ / BM, T_);

    // 1) xp = fp16(relu(x @ Wp[t]^T + bp[t]))
    gemm_f16<<<g1, blk, SMEM_BYTES>>>(
        xh, 0, D_,
        Wph, (size_t)H_ * D_,
        bp, H_,
        xp_p, (size_t)B_ * H_, H_,
        D_,
        nullptr, 0, 0, 0, /*relu*/1, /*half*/1);

    // 2) h = fp16(relu(xp @ Wop[t,idx0]^T + bop[t,idx0]))
    gemm_f16<<<g1, blk, SMEM_BYTES>>>(
        xp_p, (size_t)B_ * H_, H_,
        Woph, (size_t)NOPS_ * H_ * H_,
        bop, (size_t)NOPS_ * H_,
        h_p, (size_t)B_ * H_, H_,
        H_,
        idx_p, 0, (size_t)H_ * H_, H_, /*relu*/1, /*half*/1);

    // 3) cat[:, t*H:(t+1)*H] = fp16(relu(h @ Wop[t,idx1]^T + bop[t,idx1]))
    gemm_f16<<<g1, blk, SMEM_BYTES>>>(
        h_p, (size_t)B_ * H_, H_,
        Woph, (size_t)NOPS_ * H_ * H_,
        bop, (size_t)NOPS_ * H_,
        cat_p, (size_t)H_, T_ * H_,
        H_,
        idx_p, 1, (size_t)H_ * H_, H_, /*relu*/1, /*half*/1);

    // 4) out = cat @ Wr^T + br   (fp32 out)
    dim3 g4(O_ / BN, B_ / BM, 1);
    gemm_f16<<<g4, blk, SMEM_BYTES>>>(
        cat_p, 0, T_ * H_,
        Wrh, 0,
        br, 0,
        out, 0, O_,
        T_ * H_,
        nullptr, 0, 0, 0, /*relu*/0, /*half*/0);
}

// round 12
// speedup vs baseline: 1.1168x; 1.1168x over previous
#include <cuda_runtime.h>
#include <cuda_fp16.h>
#include <cstdint>
#include <cstddef>

// Problem constants
#define B_    8192
#define D_    1024
#define H_    2048
#define O_    1024
#define T_    4
#define NOPS_ 3

// GEMM tiling (fp16, m16n8k16): block 128x128, 8 warps, warp tile 64x32  (round-9 shape)
#define BM 128
#define BN 128
#define BK 64                    // halves; 128B row
#define LDH 72                   // BK + 8 pad -> conflict-free ldmatrix
#define STAGES 3
#define NTHREADS 256
#define SMEM_BYTES (STAGES * (BM * LDH + BN * LDH) * 2)   // 110592; 2 CTA/SM

// ---------------- scratch (static device memory, allowed) ----------------
__device__ __half g_xh  [(size_t)B_ * D_];                  // fp16 x
__device__ __half g_Wph [(size_t)T_ * H_ * D_];             // fp16 Wp
__device__ __half g_Woph[(size_t)T_ * NOPS_ * H_ * H_];     // fp16 Wop (routed experts only)
__device__ __half g_Wrh [(size_t)O_ * T_ * H_];             // fp16 Wr
__device__ __half g_xp  [(size_t)T_ * B_ * H_];             // stage-1 out
__device__ __half g_h   [(size_t)T_ * B_ * H_];             // stage-2 out
__device__ __half g_cat [(size_t)B_ * T_ * H_];             // stage-3 out, [B, T*H]
__device__ int    g_idx [T_ * 2];

// ---------------- routing: top-2 of logits per temper ----------------
__global__ void route_kernel(const float* __restrict__ logits) {
    int t = threadIdx.x;
    if (t < T_) {
        const float* l = logits + t * NOPS_;
        int i0 = 0;
        #pragma unroll
        for (int i = 1; i < NOPS_; i++) if (l[i] > l[i0]) i0 = i;
        int i1 = -1;
        #pragma unroll
        for (int i = 0; i < NOPS_; i++) {
            if (i == i0) continue;
            if (i1 < 0 || l[i] > l[i1]) i1 = i;
        }
        g_idx[t * 2 + 0] = i0;
        g_idx[t * 2 + 1] = i1;
    }
}

// ---------------- fp32 -> fp16 conversion ----------------
__global__ void cvt_half(const float4* __restrict__ src, __half* __restrict__ dst, int n4) {
    int i = blockIdx.x * blockDim.x + threadIdx.x;
    if (i < n4) {
        float4 v = src[i];
        __half2 h01 = __floats2half2_rn(v.x, v.y);
        __half2 h23 = __floats2half2_rn(v.z, v.w);
        uint2 u;
        u.x = *reinterpret_cast<uint32_t*>(&h01);
        u.y = *reinterpret_cast<uint32_t*>(&h23);
        reinterpret_cast<uint2*>(dst)[i] = u;
    }
}

// convert only the experts routing selected (z = t*NOPS+op)
__global__ void cvt_half_gated(const float4* __restrict__ src, __half* __restrict__ dst, int n4_per_z) {
    int z = blockIdx.y;
    int t = z / NOPS_, op = z % NOPS_;
    if (g_idx[t * 2] != op && g_idx[t * 2 + 1] != op) return;
    int i = blockIdx.x * blockDim.x + threadIdx.x;
    if (i < n4_per_z) {
        size_t off = (size_t)z * n4_per_z + i;
        float4 v = src[off];
        __half2 h01 = __floats2half2_rn(v.x, v.y);
        __half2 h23 = __floats2half2_rn(v.z, v.w);
        uint2 u;
        u.x = *reinterpret_cast<uint32_t*>(&h01);
        u.y = *reinterpret_cast<uint32_t*>(&h23);
        reinterpret_cast<uint2*>(dst)[off] = u;
    }
}

// ---------------- mma / ldmatrix ----------------
__device__ __forceinline__ void mma_f16(float* c, const uint32_t* a, const uint32_t* b) {
    asm volatile(
        "mma.sync.aligned.m16n8k16.row.col.f32.f16.f16.f32 "
        "{%0,%1,%2,%3}, {%4,%5,%6,%7}, {%8,%9}, {%0,%1,%2,%3};"
        : "+f"(c[0]), "+f"(c[1]), "+f"(c[2]), "+f"(c[3])
        : "r"(a[0]), "r"(a[1]), "r"(a[2]), "r"(a[3]),
          "r"(b[0]), "r"(b[1]));
}

__device__ __forceinline__ void ldsm_x4(uint32_t& r0, uint32_t& r1, uint32_t& r2, uint32_t& r3,
                                        uint32_t addr) {
    asm volatile("ldmatrix.sync.aligned.m8n8.x4.shared.b16 {%0,%1,%2,%3}, [%4];"
                 : "=r"(r0), "=r"(r1), "=r"(r2), "=r"(r3) : "r"(addr));
}

#define CP_ASYNC16(smem_u32, gptr) \
    asm volatile("cp.async.cg.shared.global [%0], [%1], 16;\n" :: "r"(smem_u32), "l"(gptr))
#define CP_COMMIT() asm volatile("cp.async.commit_group;\n" ::)
#define CP_WAIT(n)  asm volatile("cp.async.wait_group %0;\n" :: "n"(n))

// ---------------- fused fp16 GEMM: C = act(A @ W^T + bias) ----------------
__global__ void __launch_bounds__(NTHREADS, 2)
gemm_f16(const __half* __restrict__ Abase, size_t strideAz, int lda,
         const __half* __restrict__ Wbase, size_t strideWz,
         const float* __restrict__ biasBase, size_t strideBz,
         void* __restrict__ Cbase, size_t strideCz, int ldc,
         int K,
         const int* __restrict__ idxbuf, int which,
         size_t selStrideW, size_t selStrideB,
         int do_relu, int out_half)
{
    extern __shared__ __half smem[];
    __half* As = smem;                           // [STAGES][BM][LDH]
    __half* Ws = smem + STAGES * BM * LDH;       // [STAGES][BN][LDH]

    const int z = blockIdx.z;
    const __half* A    = Abase + (size_t)z * strideAz;
    const __half* W    = Wbase + (size_t)z * strideWz;
    const float*  bias = biasBase + (size_t)z * strideBz;
    if (idxbuf) {
        int sel = idxbuf[z * 2 + which];
        W    += (size_t)sel * selStrideW;
        bias += (size_t)sel * selStrideB;
    }

    const int bm = blockIdx.y * BM;
    const int bn = blockIdx.x * BN;

    const int tid  = threadIdx.x;
    const int wid  = tid >> 5;
    const int lane = tid & 31;
    const int gid  = lane >> 2;
    const int tig  = lane & 3;

    // warp grid: 2 (M) x 4 (N); warp tile 64 x 32
    const int wm = (wid & 1) * 64;
    const int wn = (wid >> 1) * 32;

    // cp.async mapping: 32 rows x 8 chunks (16B) per pass, 4 passes per tile side
    const int lr = tid >> 3;          // 0..31
    const int lc = (tid & 7) * 8;     // halves

    uint32_t As_u = (uint32_t)__cvta_generic_to_shared(As);
    uint32_t Ws_u = (uint32_t)__cvta_generic_to_shared(Ws);

    // ldmatrix per-lane base addresses (bytes), stage 0, k-step 0
    // A x4: lanes 0-7 rows 0-7 k0 | 8-15 rows 8-15 k0 | 16-23 rows 0-7 k+8 | 24-31 rows 8-15 k+8
    const int a_row  = wm + (lane & 15);
    const int a_koff = (lane >> 4) * 8;
    uint32_t lmA0 = As_u + (uint32_t)((a_row * LDH + a_koff) * 2);
    // B x4: lanes 0-7 n+0..7 k0 | 8-15 n+0..7 k+8 | 16-23 n+8..15 k0 | 24-31 n+8..15 k+8
    const int b_row  = wn + ((lane >> 4) << 3) + (lane & 7);
    const int b_koff = ((lane >> 3) & 1) * 8;
    uint32_t lmB0 = Ws_u + (uint32_t)((b_row * LDH + b_koff) * 2);

    const int numK = K / BK;

    auto load_stage = [&](int stage, int k0) {
        #pragma unroll
        for (int i = 0; i < 4; i++) {
            int r = lr + i * 32;
            const __half* srcA = A + (size_t)(bm + r) * lda + k0 + lc;
            uint32_t dstA = As_u + (uint32_t)(((stage * BM + r) * LDH + lc) * 2);
            CP_ASYNC16(dstA, srcA);
            const __half* srcW = W + (size_t)(bn + r) * lda + k0 + lc;
            uint32_t dstW = Ws_u + (uint32_t)(((stage * BN + r) * LDH + lc) * 2);
            CP_ASYNC16(dstW, srcW);
        }
    };

    float acc[4][4][4];
    #pragma unroll
    for (int mi = 0; mi < 4; mi++)
        #pragma unroll
        for (int ni = 0; ni < 4; ni++)
            #pragma unroll
            for (int i = 0; i < 4; i++) acc[mi][ni][i] = 0.0f;

    load_stage(0, 0);
    CP_COMMIT();
    load_stage(1, BK);
    CP_COMMIT();

    // double-buffered fragments (software pipeline at kk granularity)
    uint32_t af[2][4][4], bf[2][4][2];

    auto load_frags = [&](int slot, uint32_t stA, uint32_t stB, int kk) {
        #pragma unroll
        for (int mi = 0; mi < 4; mi++)
            ldsm_x4(af[slot][mi][0], af[slot][mi][1], af[slot][mi][2], af[slot][mi][3],
                    stA + (uint32_t)((mi * 16 * LDH + kk) * 2));
        #pragma unroll
        for (int nb = 0; nb < 2; nb++)
            ldsm_x4(bf[slot][2 * nb][0], bf[slot][2 * nb][1],
                    bf[slot][2 * nb + 1][0], bf[slot][2 * nb + 1][1],
                    stB + (uint32_t)((nb * 16 * LDH + kk) * 2));
    };

    for (int kt = 0; kt < numK; kt++) {
        if (kt + 1 < numK) { CP_WAIT(1); } else { CP_WAIT(0); }
        __syncthreads();          // stage kt ready; all warps done with stage kt-1

        const int nx = kt + 2;
        if (nx < numK) {
            load_stage(nx % STAGES, nx * BK);
            CP_COMMIT();
        }

        const int buf = kt % STAGES;
        const uint32_t stA = lmA0 + (uint32_t)(buf * BM * LDH * 2);
        const uint32_t stB = lmB0 + (uint32_t)(buf * BN * LDH * 2);

        load_frags(0, stA, stB, 0);

        #pragma unroll
        for (int ks = 0; ks < BK / 16; ks++) {
            const int cur = ks & 1;
            if (ks + 1 < BK / 16)
                load_frags(cur ^ 1, stA, stB, (ks + 1) * 16);
            #pragma unroll
            for (int mi = 0; mi < 4; mi++)
                #pragma unroll
                for (int ni = 0; ni < 4; ni++)
                    mma_f16(acc[mi][ni], af[cur][mi], bf[cur][ni]);
        }
    }

    // epilogue: bias + optional relu; store fp16 (intermediate) or fp32 (final)
    #pragma unroll
    for (int mi = 0; mi < 4; mi++) {
        const int row0 = bm + wm + mi * 16 + gid;
        #pragma unroll
        for (int ni = 0; ni < 4; ni++) {
            const int col = bn + wn + ni * 8 + tig * 2;
            float b0 = bias[col];
            float b1 = bias[col + 1];
            float v0 = acc[mi][ni][0] + b0;
            float v1 = acc[mi][ni][1] + b1;
            float v2 = acc[mi][ni][2] + b0;
            float v3 = acc[mi][ni][3] + b1;
            if (do_relu) {
                v0 = fmaxf(v0, 0.0f); v1 = fmaxf(v1, 0.0f);
                v2 = fmaxf(v2, 0.0f); v3 = fmaxf(v3, 0.0f);
            }
            if (out_half) {
                __half* C = (__half*)Cbase + (size_t)z * strideCz;
                __half2 h0 = __floats2half2_rn(v0, v1);
                __half2 h1 = __floats2half2_rn(v2, v3);
                *reinterpret_cast<__half2*>(C + (size_t)row0 * ldc + col) = h0;
                *reinterpret_cast<__half2*>(C + (size_t)(row0 + 8) * ldc + col) = h1;
            } else {
                float* C = (float*)Cbase + (size_t)z * strideCz;
                *reinterpret_cast<float2*>(C + (size_t)row0 * ldc + col) = make_float2(v0, v1);
                *reinterpret_cast<float2*>(C + (size_t)(row0 + 8) * ldc + col) = make_float2(v2, v3);
            }
        }
    }
}

// ---------------- launch ----------------
extern "C" void kernel_launch(void* const* d_in, const int* in_sizes, int n_in,
                              void* d_out, int out_size)
{
    const float* x      = (const float*)d_in[0];
    const float* Wp     = (const float*)d_in[1];
    const float* bp     = (const float*)d_in[2];
    const float* Wop    = (const float*)d_in[3];
    const float* bop    = (const float*)d_in[4];
    const float* logits = (const float*)d_in[5];
    const float* Wr     = (const float*)d_in[6];
    const float* br     = (const float*)d_in[7];
    float* out = (float*)d_out;

    cudaFuncSetAttribute(gemm_f16, cudaFuncAttributeMaxDynamicSharedMemorySize, SMEM_BYTES);

    __half *xh, *Wph, *Woph, *Wrh, *xp_p, *h_p, *cat_p;
    int* idx_p;
    cudaGetSymbolAddress((void**)&xh,    g_xh);
    cudaGetSymbolAddress((void**)&Wph,   g_Wph);
    cudaGetSymbolAddress((void**)&Woph,  g_Woph);
    cudaGetSymbolAddress((void**)&Wrh,   g_Wrh);
    cudaGetSymbolAddress((void**)&xp_p,  g_xp);
    cudaGetSymbolAddress((void**)&h_p,   g_h);
    cudaGetSymbolAddress((void**)&cat_p, g_cat);
    cudaGetSymbolAddress((void**)&idx_p, g_idx);

    route_kernel<<<1, 32>>>(logits);

    // fp32 -> fp16 operand conversion
    {
        int n4;
        n4 = (B_ * D_) / 4;
        cvt_half<<<(n4 + 255) / 256, 256>>>((const float4*)x, xh, n4);
        n4 = (T_ * H_ * D_) / 4;
        cvt_half<<<(n4 + 255) / 256, 256>>>((const float4*)Wp, Wph, n4);
        n4 = (O_ * T_ * H_) / 4;
        cvt_half<<<(n4 + 255) / 256, 256>>>((const float4*)Wr, Wrh, n4);
        int n4z = (H_ * H_) / 4;
        dim3 g((n4z + 255) / 256, T_ * NOPS_);
        cvt_half_gated<<<g, 256>>>((const float4*)Wop, Woph, n4z);
    }

    dim3 blk(NTHREADS);
    dim3 g1(H_ / BN, B_ / BM, T_);

    // 1) xp = fp16(relu(x @ Wp[t]^T + bp[t]))
    gemm_f16<<<g1, blk, SMEM_BYTES>>>(
        xh, 0, D_,
        Wph, (size_t)H_ * D_,
        bp, H_,
        xp_p, (size_t)B_ * H_, H_,
        D_,
        nullptr, 0, 0, 0, /*relu*/1, /*half*/1);

    // 2) h = fp16(relu(xp @ Wop[t,idx0]^T + bop[t,idx0]))
    gemm_f16<<<g1, blk, SMEM_BYTES>>>(
        xp_p, (size_t)B_ * H_, H_,
        Woph, (size_t)NOPS_ * H_ * H_,
        bop, (size_t)NOPS_ * H_,
        h_p, (size_t)B_ * H_, H_,
        H_,
        idx_p, 0, (size_t)H_ * H_, H_, /*relu*/1, /*half*/1);

    // 3) cat[:, t*H:(t+1)*H] = fp16(relu(h @ Wop[t,idx1]^T + bop[t,idx1]))
    gemm_f16<<<g1, blk, SMEM_BYTES>>>(
        h_p, (size_t)B_ * H_, H_,
        Woph, (size_t)NOPS_ * H_ * H_,
        bop, (size_t)NOPS_ * H_,
        cat_p, (size_t)H_, T_ * H_,
        H_,
        idx_p, 1, (size_t)H_ * H_, H_, /*relu*/1, /*half*/1);

    // 4) out = cat @ Wr^T + br   (fp32 out)
    dim3 g4(O_ / BN, B_ / BM, 1);
    gemm_f16<<<g4, blk, SMEM_BYTES>>>(
        cat_p, 0, T_ * H_,
        Wrh, 0,
        br, 0,
        out, 0, O_,
        T_ * H_,
        nullptr, 0, 0, 0, /*relu*/0, /*half*/0);
}

// round 13
// speedup vs baseline: 1.1773x; 1.0542x over previous
#include <cuda_runtime.h>
#include <cuda_fp16.h>
#include <cstdint>
#include <cstddef>

// Problem constants
#define B_    8192
#define D_    1024
#define H_    2048
#define O_    1024
#define T_    4
#define NOPS_ 3

// GEMM tiling (fp16, m16n8k16): block 128x128, 8 warps, warp tile 64x32  (round-9 shape)
#define BM 128
#define BN 128
#define BK 64                    // halves; 128B row
#define LDH 72                   // BK + 8 pad -> conflict-free ldmatrix
#define STAGES 3
#define NTHREADS 256
#define SMEM_BYTES (STAGES * (BM * LDH + BN * LDH) * 2)   // 110592; 2 CTA/SM

// ---------------- scratch (static device memory, allowed) ----------------
__device__ __half g_xh  [(size_t)B_ * D_];                  // fp16 x
__device__ __half g_Wph [(size_t)T_ * H_ * D_];             // fp16 Wp
__device__ __half g_Woph[(size_t)T_ * NOPS_ * H_ * H_];     // fp16 Wop (routed experts only)
__device__ __half g_Wrh [(size_t)O_ * T_ * H_];             // fp16 Wr
__device__ __half g_xp  [(size_t)T_ * B_ * H_];             // stage-1 out
__device__ __half g_h   [(size_t)T_ * B_ * H_];             // stage-2 out
__device__ __half g_cat [(size_t)B_ * T_ * H_];             // stage-3 out, [B, T*H]
__device__ int    g_idx [T_ * 2];

// ---------------- routing: top-2 of logits per temper ----------------
__global__ void route_kernel(const float* __restrict__ logits) {
    int t = threadIdx.x;
    if (t < T_) {
        const float* l = logits + t * NOPS_;
        int i0 = 0;
        #pragma unroll
        for (int i = 1; i < NOPS_; i++) if (l[i] > l[i0]) i0 = i;
        int i1 = -1;
        #pragma unroll
        for (int i = 0; i < NOPS_; i++) {
            if (i == i0) continue;
            if (i1 < 0 || l[i] > l[i1]) i1 = i;
        }
        g_idx[t * 2 + 0] = i0;
        g_idx[t * 2 + 1] = i1;
    }
}

// ---------------- fused fp32 -> fp16 conversion (single launch) ----------------
// region layout in float4 blocks of 256 threads:
//   [0, NBX)            : x      (B*D)
//   [NBX, +NBWP)        : Wp     (T*H*D)
//   [.., +NBWR)         : Wr     (O*T*H)
//   [.., +12*NBOP)      : Wop    per expert z, gated on g_idx (route ran before us)
#define NBX   ((B_ * D_ / 4) / 256)                 // 8192
#define NBWP  ((T_ * H_ * D_ / 4) / 256)            // 8192
#define NBWR  ((O_ * T_ * H_ / 4) / 256)            // 8192
#define NBOP  ((H_ * H_ / 4) / 256)                 // 4096
#define NB_TOTAL (NBX + NBWP + NBWR + T_ * NOPS_ * NBOP)

__device__ __forceinline__ void cvt4(const float4* __restrict__ src, __half* __restrict__ dst,
                                     size_t i4) {
    float4 v = src[i4];
    __half2 h01 = __floats2half2_rn(v.x, v.y);
    __half2 h23 = __floats2half2_rn(v.z, v.w);
    uint2 u;
    u.x = *reinterpret_cast<uint32_t*>(&h01);
    u.y = *reinterpret_cast<uint32_t*>(&h23);
    reinterpret_cast<uint2*>(dst)[i4] = u;
}

__global__ void prep_kernel(const float* __restrict__ x,  const float* __restrict__ Wp,
                            const float* __restrict__ Wr, const float* __restrict__ Wop)
{
    int b = blockIdx.x;
    if (b < NBX) {
        cvt4((const float4*)x, g_xh, (size_t)b * 256 + threadIdx.x);
        return;
    }
    b -= NBX;
    if (b < NBWP) {
        cvt4((const float4*)Wp, g_Wph, (size_t)b * 256 + threadIdx.x);
        return;
    }
    b -= NBWP;
    if (b < NBWR) {
        cvt4((const float4*)Wr, g_Wrh, (size_t)b * 256 + threadIdx.x);
        return;
    }
    b -= NBWR;
    {
        int z = b / NBOP;                 // 0..11 expert slot (t*NOPS+op)
        int t = z / NOPS_, op = z % NOPS_;
        if (g_idx[t * 2] != op && g_idx[t * 2 + 1] != op) return;   // unrouted expert
        size_t i4 = (size_t)z * (H_ * H_ / 4) + (size_t)(b % NBOP) * 256 + threadIdx.x;
        cvt4((const float4*)Wop, g_Woph, i4);
    }
}

// ---------------- mma / ldmatrix ----------------
__device__ __forceinline__ void mma_f16(float* c, const uint32_t* a, const uint32_t* b) {
    asm volatile(
        "mma.sync.aligned.m16n8k16.row.col.f32.f16.f16.f32 "
        "{%0,%1,%2,%3}, {%4,%5,%6,%7}, {%8,%9}, {%0,%1,%2,%3};"
        : "+f"(c[0]), "+f"(c[1]), "+f"(c[2]), "+f"(c[3])
        : "r"(a[0]), "r"(a[1]), "r"(a[2]), "r"(a[3]),
          "r"(b[0]), "r"(b[1]));
}

__device__ __forceinline__ void ldsm_x4(uint32_t& r0, uint32_t& r1, uint32_t& r2, uint32_t& r3,
                                        uint32_t addr) {
    asm volatile("ldmatrix.sync.aligned.m8n8.x4.shared.b16 {%0,%1,%2,%3}, [%4];"
                 : "=r"(r0), "=r"(r1), "=r"(r2), "=r"(r3) : "r"(addr));
}

#define CP_ASYNC16(smem_u32, gptr) \
    asm volatile("cp.async.cg.shared.global [%0], [%1], 16;\n" :: "r"(smem_u32), "l"(gptr))
#define CP_COMMIT() asm volatile("cp.async.commit_group;\n" ::)
#define CP_WAIT(n)  asm volatile("cp.async.wait_group %0;\n" :: "n"(n))

// ---------------- fused fp16 GEMM: C = act(A @ W^T + bias) ---- (exact round-9 mainloop) ----
__global__ void __launch_bounds__(NTHREADS, 2)
gemm_f16(const __half* __restrict__ Abase, size_t strideAz, int lda,
         const __half* __restrict__ Wbase, size_t strideWz,
         const float* __restrict__ biasBase, size_t strideBz,
         void* __restrict__ Cbase, size_t strideCz, int ldc,
         int K,
         const int* __restrict__ idxbuf, int which,
         size_t selStrideW, size_t selStrideB,
         int do_relu, int out_half)
{
    extern __shared__ __half smem[];
    __half* As = smem;                           // [STAGES][BM][LDH]
    __half* Ws = smem + STAGES * BM * LDH;       // [STAGES][BN][LDH]

    const int z = blockIdx.z;
    const __half* A    = Abase + (size_t)z * strideAz;
    const __half* W    = Wbase + (size_t)z * strideWz;
    const float*  bias = biasBase + (size_t)z * strideBz;
    if (idxbuf) {
        int sel = idxbuf[z * 2 + which];
        W    += (size_t)sel * selStrideW;
        bias += (size_t)sel * selStrideB;
    }

    const int bm = blockIdx.y * BM;
    const int bn = blockIdx.x * BN;

    const int tid  = threadIdx.x;
    const int wid  = tid >> 5;
    const int lane = tid & 31;
    const int gid  = lane >> 2;
    const int tig  = lane & 3;

    // warp grid: 2 (M) x 4 (N); warp tile 64 x 32
    const int wm = (wid & 1) * 64;
    const int wn = (wid >> 1) * 32;

    // cp.async mapping: 32 rows x 8 chunks (16B) per pass, 4 passes per tile side
    const int lr = tid >> 3;          // 0..31
    const int lc = (tid & 7) * 8;     // halves

    uint32_t As_u = (uint32_t)__cvta_generic_to_shared(As);
    uint32_t Ws_u = (uint32_t)__cvta_generic_to_shared(Ws);

    // ldmatrix per-lane base addresses (bytes), stage 0, k-step 0
    const int a_row  = wm + (lane & 15);
    const int a_koff = (lane >> 4) * 8;
    uint32_t lmA0 = As_u + (uint32_t)((a_row * LDH + a_koff) * 2);
    const int b_row  = wn + ((lane >> 4) << 3) + (lane & 7);
    const int b_koff = ((lane >> 3) & 1) * 8;
    uint32_t lmB0 = Ws_u + (uint32_t)((b_row * LDH + b_koff) * 2);

    const int numK = K / BK;

    auto load_stage = [&](int stage, int k0) {
        #pragma unroll
        for (int i = 0; i < 4; i++) {
            int r = lr + i * 32;
            const __half* srcA = A + (size_t)(bm + r) * lda + k0 + lc;
            uint32_t dstA = As_u + (uint32_t)(((stage * BM + r) * LDH + lc) * 2);
            CP_ASYNC16(dstA, srcA);
            const __half* srcW = W + (size_t)(bn + r) * lda + k0 + lc;
            uint32_t dstW = Ws_u + (uint32_t)(((stage * BN + r) * LDH + lc) * 2);
            CP_ASYNC16(dstW, srcW);
        }
    };

    float acc[4][4][4];
    #pragma unroll
    for (int mi = 0; mi < 4; mi++)
        #pragma unroll
        for (int ni = 0; ni < 4; ni++)
            #pragma unroll
            for (int i = 0; i < 4; i++) acc[mi][ni][i] = 0.0f;

    load_stage(0, 0);
    CP_COMMIT();
    load_stage(1, BK);
    CP_COMMIT();

    for (int kt = 0; kt < numK; kt++) {
        if (kt + 1 < numK) { CP_WAIT(1); } else { CP_WAIT(0); }
        __syncthreads();          // stage kt ready; all warps done with stage kt-1

        const int nx = kt + 2;
        if (nx < numK) {
            load_stage(nx % STAGES, nx * BK);
            CP_COMMIT();
        }

        const int buf = kt % STAGES;
        const uint32_t stA = lmA0 + (uint32_t)(buf * BM * LDH * 2);
        const uint32_t stB = lmB0 + (uint32_t)(buf * BN * LDH * 2);

        #pragma unroll
        for (int kk = 0; kk < BK; kk += 16) {
            uint32_t af[4][4], bf[4][2];
            #pragma unroll
            for (int mi = 0; mi < 4; mi++)
                ldsm_x4(af[mi][0], af[mi][1], af[mi][2], af[mi][3],
                        stA + (uint32_t)((mi * 16 * LDH + kk) * 2));
            #pragma unroll
            for (int nb = 0; nb < 2; nb++)
                ldsm_x4(bf[2 * nb][0], bf[2 * nb][1], bf[2 * nb + 1][0], bf[2 * nb + 1][1],
                        stB + (uint32_t)((nb * 16 * LDH + kk) * 2));
            #pragma unroll
            for (int mi = 0; mi < 4; mi++)
                #pragma unroll
                for (int ni = 0; ni < 4; ni++)
                    mma_f16(acc[mi][ni], af[mi], bf[ni]);
        }
    }

    // epilogue: bias + optional relu; store fp16 (intermediate) or fp32 (final)
    #pragma unroll
    for (int mi = 0; mi < 4; mi++) {
        const int row0 = bm + wm + mi * 16 + gid;
        #pragma unroll
        for (int ni = 0; ni < 4; ni++) {
            const int col = bn + wn + ni * 8 + tig * 2;
            float b0 = bias[col];
            float b1 = bias[col + 1];
            float v0 = acc[mi][ni][0] + b0;
            float v1 = acc[mi][ni][1] + b1;
            float v2 = acc[mi][ni][2] + b0;
            float v3 = acc[mi][ni][3] + b1;
            if (do_relu) {
                v0 = fmaxf(v0, 0.0f); v1 = fmaxf(v1, 0.0f);
                v2 = fmaxf(v2, 0.0f); v3 = fmaxf(v3, 0.0f);
            }
            if (out_half) {
                __half* C = (__half*)Cbase + (size_t)z * strideCz;
                __half2 h0 = __floats2half2_rn(v0, v1);
                __half2 h1 = __floats2half2_rn(v2, v3);
                *reinterpret_cast<__half2*>(C + (size_t)row0 * ldc + col) = h0;
                *reinterpret_cast<__half2*>(C + (size_t)(row0 + 8) * ldc + col) = h1;
            } else {
                float* C = (float*)Cbase + (size_t)z * strideCz;
                *reinterpret_cast<float2*>(C + (size_t)row0 * ldc + col) = make_float2(v0, v1);
                *reinterpret_cast<float2*>(C + (size_t)(row0 + 8) * ldc + col) = make_float2(v2, v3);
            }
        }
    }
}

// ---------------- launch ----------------
extern "C" void kernel_launch(void* const* d_in, const int* in_sizes, int n_in,
                              void* d_out, int out_size)
{
    const float* x      = (const float*)d_in[0];
    const float* Wp     = (const float*)d_in[1];
    const float* bp     = (const float*)d_in[2];
    const float* Wop    = (const float*)d_in[3];
    const float* bop    = (const float*)d_in[4];
    const float* logits = (const float*)d_in[5];
    const float* Wr     = (const float*)d_in[6];
    const float* br     = (const float*)d_in[7];
    float* out = (float*)d_out;

    cudaFuncSetAttribute(gemm_f16, cudaFuncAttributeMaxDynamicSharedMemorySize, SMEM_BYTES);

    __half *xh, *Wph, *Woph, *Wrh, *xp_p, *h_p, *cat_p;
    int* idx_p;
    cudaGetSymbolAddress((void**)&xh,    g_xh);
    cudaGetSymbolAddress((void**)&Wph,   g_Wph);
    cudaGetSymbolAddress((void**)&Woph,  g_Woph);
    cudaGetSymbolAddress((void**)&Wrh,   g_Wrh);
    cudaGetSymbolAddress((void**)&xp_p,  g_xp);
    cudaGetSymbolAddress((void**)&h_p,   g_h);
    cudaGetSymbolAddress((void**)&cat_p, g_cat);
    cudaGetSymbolAddress((void**)&idx_p, g_idx);

    // launch 0: routing (g_idx)
    route_kernel<<<1, 32>>>(logits);

    // launch 1: all fp32->fp16 conversions in one grid (Wop gated on g_idx)
    prep_kernel<<<NB_TOTAL, 256>>>(x, Wp, Wr, Wop);

    dim3 blk(NTHREADS);
    dim3 g1(H_ / BN, B_ / BM, T_);

    // launch 2: xp = fp16(relu(x @ Wp[t]^T + bp[t]))
    gemm_f16<<<g1, blk, SMEM_BYTES>>>(
        xh, 0, D_,
        Wph, (size_t)H_ * D_,
        bp, H_,
        xp_p, (size_t)B_ * H_, H_,
        D_,
        nullptr, 0, 0, 0, /*relu*/1, /*half*/1);

    // launch 3: h = fp16(relu(xp @ Wop[t,idx0]^T + bop[t,idx0]))
    gemm_f16<<<g1, blk, SMEM_BYTES>>>(
        xp_p, (size_t)B_ * H_, H_,
        Woph, (size_t)NOPS_ * H_ * H_,
        bop, (size_t)NOPS_ * H_,
        h_p, (size_t)B_ * H_, H_,
        H_,
        idx_p, 0, (size_t)H_ * H_, H_, /*relu*/1, /*half*/1);

    // launch 4: cat[:, t*H:(t+1)*H] = fp16(relu(h @ Wop[t,idx1]^T + bop[t,idx1]))
    gemm_f16<<<g1, blk, SMEM_BYTES>>>(
        h_p, (size_t)B_ * H_, H_,
        Woph, (size_t)NOPS_ * H_ * H_,
        bop, (size_t)NOPS_ * H_,
        cat_p, (size_t)H_, T_ * H_,
        H_,
        idx_p, 1, (size_t)H_ * H_, H_, /*relu*/1, /*half*/1);

    // launch 5: out = cat @ Wr^T + br   (fp32 out)  — ncu -s 5 lands here
    dim3 g4(O_ / BN, B_ / BM, 1);
    gemm_f16<<<g4, blk, SMEM_BYTES>>>(
        cat_p, 0, T_ * H_,
        Wrh, 0,
        br, 0,
        out, 0, O_,
        T_ * H_,
        nullptr, 0, 0, 0, /*relu*/0, /*half*/0);
}

// round 15
// speedup vs baseline: 1.2871x; 1.0933x over previous
#include <cuda_runtime.h>
#include <cuda_fp16.h>
#include <cstdint>
#include <cstddef>

// Problem constants
#define B_    8192
#define D_    1024
#define H_    2048
#define O_    1024
#define T_    4
#define NOPS_ 3

// GEMM tiling (fp16, m16n8k16): block 128x128, 8 warps, warp tile 64x32
#define BM 128
#define BN 128
#define BK 64                    // halves; 128B row
#define LDH 72                   // BK + 8 pad -> conflict-free ldmatrix
#define STAGES 3
#define NTHREADS 256
#define SMEM_BYTES (STAGES * (BM * LDH + BN * LDH) * 2)   // 110592; 2 CTA/SM

// ---------------- scratch (static device memory, allowed) ----------------
__device__ __half g_xh  [(size_t)B_ * D_];                  // fp16 x
__device__ __half g_Wph [(size_t)T_ * H_ * D_];             // fp16 Wp
__device__ __half g_Woph[(size_t)T_ * NOPS_ * H_ * H_];     // fp16 Wop (routed experts only)
__device__ __half g_Wrh [(size_t)O_ * T_ * H_];             // fp16 Wr
__device__ __half g_xp  [(size_t)T_ * B_ * H_];             // stage-1 out
__device__ __half g_h   [(size_t)T_ * B_ * H_];             // stage-2 out
__device__ __half g_cat [(size_t)B_ * T_ * H_];             // stage-3 out, [B, T*H]
__device__ int    g_idx [T_ * 2];

// ---------------- routing: top-2 of logits per temper ----------------
__global__ void route_kernel(const float* __restrict__ logits) {
    int t = threadIdx.x;
    if (t < T_) {
        const float* l = logits + t * NOPS_;
        int i0 = 0;
        #pragma unroll
        for (int i = 1; i < NOPS_; i++) if (l[i] > l[i0]) i0 = i;
        int i1 = -1;
        #pragma unroll
        for (int i = 0; i < NOPS_; i++) {
            if (i == i0) continue;
            if (i1 < 0 || l[i] > l[i1]) i1 = i;
        }
        g_idx[t * 2 + 0] = i0;
        g_idx[t * 2 + 1] = i1;
    }
}

// ---------------- fused fp32 -> fp16 conversion (single launch) ----------------
#define NBX   ((B_ * D_ / 4) / 256)                 // 8192
#define NBWP  ((T_ * H_ * D_ / 4) / 256)            // 8192
#define NBWR  ((O_ * T_ * H_ / 4) / 256)            // 8192
#define NBOP  ((H_ * H_ / 4) / 256)                 // 4096
#define NB_TOTAL (NBX + NBWP + NBWR + T_ * NOPS_ * NBOP)

__device__ __forceinline__ void cvt4(const float4* __restrict__ src, __half* __restrict__ dst,
                                     size_t i4) {
    float4 v = src[i4];
    __half2 h01 = __floats2half2_rn(v.x, v.y);
    __half2 h23 = __floats2half2_rn(v.z, v.w);
    uint2 u;
    u.x = *reinterpret_cast<uint32_t*>(&h01);
    u.y = *reinterpret_cast<uint32_t*>(&h23);
    reinterpret_cast<uint2*>(dst)[i4] = u;
}

__global__ void prep_kernel(const float* __restrict__ x,  const float* __restrict__ Wp,
                            const float* __restrict__ Wr, const float* __restrict__ Wop)
{
    int b = blockIdx.x;
    if (b < NBX) {
        cvt4((const float4*)x, g_xh, (size_t)b * 256 + threadIdx.x);
        return;
    }
    b -= NBX;
    if (b < NBWP) {
        cvt4((const float4*)Wp, g_Wph, (size_t)b * 256 + threadIdx.x);
        return;
    }
    b -= NBWP;
    if (b < NBWR) {
        cvt4((const float4*)Wr, g_Wrh, (size_t)b * 256 + threadIdx.x);
        return;
    }
    b -= NBWR;
    {
        int z = b / NBOP;                 // 0..11 expert slot (t*NOPS+op)
        int t = z / NOPS_, op = z % NOPS_;
        if (g_idx[t * 2] != op && g_idx[t * 2 + 1] != op) return;   // unrouted expert
        size_t i4 = (size_t)z * (H_ * H_ / 4) + (size_t)(b % NBOP) * 256 + threadIdx.x;
        cvt4((const float4*)Wop, g_Woph, i4);
    }
}

// ---------------- mma / ldmatrix ----------------
__device__ __forceinline__ void mma_f16(float* c, const uint32_t* a, const uint32_t* b) {
    asm volatile(
        "mma.sync.aligned.m16n8k16.row.col.f32.f16.f16.f32 "
        "{%0,%1,%2,%3}, {%4,%5,%6,%7}, {%8,%9}, {%0,%1,%2,%3};"
        : "+f"(c[0]), "+f"(c[1]), "+f"(c[2]), "+f"(c[3])
        : "r"(a[0]), "r"(a[1]), "r"(a[2]), "r"(a[3]),
          "r"(b[0]), "r"(b[1]));
}

__device__ __forceinline__ void ldsm_x4(uint32_t& r0, uint32_t& r1, uint32_t& r2, uint32_t& r3,
                                        uint32_t addr) {
    asm volatile("ldmatrix.sync.aligned.m8n8.x4.shared.b16 {%0,%1,%2,%3}, [%4];"
                 : "=r"(r0), "=r"(r1), "=r"(r2), "=r"(r3) : "r"(addr));
}

#define CP_ASYNC16(smem_u32, gptr) \
    asm volatile("cp.async.cg.shared.global [%0], [%1], 16;\n" :: "r"(smem_u32), "l"(gptr))
#define CP_COMMIT() asm volatile("cp.async.commit_group;\n" ::)
#define CP_WAIT(n)  asm volatile("cp.async.wait_group %0;\n" :: "n"(n))

// ---------------- fused fp16 GEMM: C = act(A @ W^T + bias) ----------------
__global__ void __launch_bounds__(NTHREADS, 2)
gemm_f16(const __half* __restrict__ Abase, size_t strideAz, int lda,
         const __half* __restrict__ Wbase, size_t strideWz,
         const float* __restrict__ biasBase, size_t strideBz,
         void* __restrict__ Cbase, size_t strideCz, int ldc,
         int K,
         const int* __restrict__ idxbuf, int which,
         size_t selStrideW, size_t selStrideB,
         int do_relu, int out_half)
{
    extern __shared__ __half smem[];
    __half* As = smem;                           // [STAGES][BM][LDH]
    __half* Ws = smem + STAGES * BM * LDH;       // [STAGES][BN][LDH]

    const int z = blockIdx.z;
    const __half* A    = Abase + (size_t)z * strideAz;
    const __half* W    = Wbase + (size_t)z * strideWz;
    const float*  bias = biasBase + (size_t)z * strideBz;
    if (idxbuf) {
        int sel = idxbuf[z * 2 + which];
        W    += (size_t)sel * selStrideW;
        bias += (size_t)sel * selStrideB;
    }

    const int bm = blockIdx.y * BM;
    const int bn = blockIdx.x * BN;

    const int tid  = threadIdx.x;
    const int wid  = tid >> 5;
    const int lane = tid & 31;
    const int gid  = lane >> 2;
    const int tig  = lane & 3;

    // warp grid: 2 (M) x 4 (N); warp tile 64 x 32
    const int wm = (wid & 1) * 64;
    const int wn = (wid >> 1) * 32;

    // cp.async mapping: 32 rows x 8 chunks (16B) per pass, 4 passes per tile side
    const int lr = tid >> 3;          // 0..31
    const int lc = (tid & 7) * 8;     // halves

    uint32_t As_u = (uint32_t)__cvta_generic_to_shared(As);
    uint32_t Ws_u = (uint32_t)__cvta_generic_to_shared(Ws);

    // ldmatrix per-lane base addresses (bytes), stage 0, k-step 0
    const int a_row  = wm + (lane & 15);
    const int a_koff = (lane >> 4) * 8;
    uint32_t lmA0 = As_u + (uint32_t)((a_row * LDH + a_koff) * 2);
    const int b_row  = wn + ((lane >> 4) << 3) + (lane & 7);
    const int b_koff = ((lane >> 3) & 1) * 8;
    uint32_t lmB0 = Ws_u + (uint32_t)((b_row * LDH + b_koff) * 2);

    const int numK = K / BK;

    auto load_stage = [&](int stage, int k0) {
        #pragma unroll
        for (int i = 0; i < 4; i++) {
            int r = lr + i * 32;
            const __half* srcA = A + (size_t)(bm + r) * lda + k0 + lc;
            uint32_t dstA = As_u + (uint32_t)(((stage * BM + r) * LDH + lc) * 2);
            CP_ASYNC16(dstA, srcA);
            const __half* srcW = W + (size_t)(bn + r) * lda + k0 + lc;
            uint32_t dstW = Ws_u + (uint32_t)(((stage * BN + r) * LDH + lc) * 2);
            CP_ASYNC16(dstW, srcW);
        }
    };

    float acc[4][4][4];
    #pragma unroll
    for (int mi = 0; mi < 4; mi++)
        #pragma unroll
        for (int ni = 0; ni < 4; ni++)
            #pragma unroll
            for (int i = 0; i < 4; i++) acc[mi][ni][i] = 0.0f;

    load_stage(0, 0);
    CP_COMMIT();
    load_stage(1, BK);
    CP_COMMIT();

    for (int kt = 0; kt < numK; kt++) {
        if (kt + 1 < numK) { CP_WAIT(1); } else { CP_WAIT(0); }
        __syncthreads();          // stage kt ready; all warps done with stage kt-1

        const int buf = kt % STAGES;
        const uint32_t stA = lmA0 + (uint32_t)(buf * BM * LDH * 2);
        const uint32_t stB = lmB0 + (uint32_t)(buf * BN * LDH * 2);

        // ---- kk = 0 first: get the tensor pipe going before the cp.async burst ----
        {
            uint32_t af[4][4], bf[4][2];
            #pragma unroll
            for (int mi = 0; mi < 4; mi++)
                ldsm_x4(af[mi][0], af[mi][1], af[mi][2], af[mi][3],
                        stA + (uint32_t)((mi * 16 * LDH) * 2));
            #pragma unroll
            for (int nb = 0; nb < 2; nb++)
                ldsm_x4(bf[2 * nb][0], bf[2 * nb][1], bf[2 * nb + 1][0], bf[2 * nb + 1][1],
                        stB + (uint32_t)((nb * 16 * LDH) * 2));
            #pragma unroll
            for (int mi = 0; mi < 4; mi++)
                #pragma unroll
                for (int ni = 0; ni < 4; ni++)
                    mma_f16(acc[mi][ni], af[mi], bf[ni]);
        }

        // ---- prefetch stage kt+2 under the MMA shadow ----
        const int nx = kt + 2;
        if (nx < numK) {
            load_stage(nx % STAGES, nx * BK);
            CP_COMMIT();
        }

        // ---- kk = 16, 32, 48 ----
        #pragma unroll
        for (int kk = 16; kk < BK; kk += 16) {
            uint32_t af[4][4], bf[4][2];
            #pragma unroll
            for (int mi = 0; mi < 4; mi++)
                ldsm_x4(af[mi][0], af[mi][1], af[mi][2], af[mi][3],
                        stA + (uint32_t)((mi * 16 * LDH + kk) * 2));
            #pragma unroll
            for (int nb = 0; nb < 2; nb++)
                ldsm_x4(bf[2 * nb][0], bf[2 * nb][1], bf[2 * nb + 1][0], bf[2 * nb + 1][1],
                        stB + (uint32_t)((nb * 16 * LDH + kk) * 2));
            #pragma unroll
            for (int mi = 0; mi < 4; mi++)
                #pragma unroll
                for (int ni = 0; ni < 4; ni++)
                    mma_f16(acc[mi][ni], af[mi], bf[ni]);
        }
    }

    // epilogue: bias + optional relu; store fp16 (intermediate) or fp32 (final)
    #pragma unroll
    for (int mi = 0; mi < 4; mi++) {
        const int row0 = bm + wm + mi * 16 + gid;
        #pragma unroll
        for (int ni = 0; ni < 4; ni++) {
            const int col = bn + wn + ni * 8 + tig * 2;
            float b0 = bias[col];
            float b1 = bias[col + 1];
            float v0 = acc[mi][ni][0] + b0;
            float v1 = acc[mi][ni][1] + b1;
            float v2 = acc[mi][ni][2] + b0;
            float v3 = acc[mi][ni][3] + b1;
            if (do_relu) {
                v0 = fmaxf(v0, 0.0f); v1 = fmaxf(v1, 0.0f);
                v2 = fmaxf(v2, 0.0f); v3 = fmaxf(v3, 0.0f);
            }
            if (out_half) {
                __half* C = (__half*)Cbase + (size_t)z * strideCz;
                __half2 h0 = __floats2half2_rn(v0, v1);
                __half2 h1 = __floats2half2_rn(v2, v3);
                *reinterpret_cast<__half2*>(C + (size_t)row0 * ldc + col) = h0;
                *reinterpret_cast<__half2*>(C + (size_t)(row0 + 8) * ldc + col) = h1;
            } else {
                float* C = (float*)Cbase + (size_t)z * strideCz;
                *reinterpret_cast<float2*>(C + (size_t)row0 * ldc + col) = make_float2(v0, v1);
                *reinterpret_cast<float2*>(C + (size_t)(row0 + 8) * ldc + col) = make_float2(v2, v3);
            }
        }
    }
}

// ---------------- launch ----------------
extern "C" void kernel_launch(void* const* d_in, const int* in_sizes, int n_in,
                              void* d_out, int out_size)
{
    const float* x      = (const float*)d_in[0];
    const float* Wp     = (const float*)d_in[1];
    const float* bp     = (const float*)d_in[2];
    const float* Wop    = (const float*)d_in[3];
    const float* bop    = (const float*)d_in[4];
    const float* logits = (const float*)d_in[5];
    const float* Wr     = (const float*)d_in[6];
    const float* br     = (const float*)d_in[7];
    float* out = (float*)d_out;

    cudaFuncSetAttribute(gemm_f16, cudaFuncAttributeMaxDynamicSharedMemorySize, SMEM_BYTES);

    __half *xh, *Wph, *Woph, *Wrh, *xp_p, *h_p, *cat_p;
    int* idx_p;
    cudaGetSymbolAddress((void**)&xh,    g_xh);
    cudaGetSymbolAddress((void**)&Wph,   g_Wph);
    cudaGetSymbolAddress((void**)&Woph,  g_Woph);
    cudaGetSymbolAddress((void**)&Wrh,   g_Wrh);
    cudaGetSymbolAddress((void**)&xp_p,  g_xp);
    cudaGetSymbolAddress((void**)&h_p,   g_h);
    cudaGetSymbolAddress((void**)&cat_p, g_cat);
    cudaGetSymbolAddress((void**)&idx_p, g_idx);

    // launch 0: routing (g_idx)
    route_kernel<<<1, 32>>>(logits);

    // launch 1: all fp32->fp16 conversions in one grid (Wop gated on g_idx)
    prep_kernel<<<NB_TOTAL, 256>>>(x, Wp, Wr, Wop);

    dim3 blk(NTHREADS);
    dim3 g1(H_ / BN, B_ / BM, T_);

    // launch 2: xp = fp16(relu(x @ Wp[t]^T + bp[t]))
    gemm_f16<<<g1, blk, SMEM_BYTES>>>(
        xh, 0, D_,
        Wph, (size_t)H_ * D_,
        bp, H_,
        xp_p, (size_t)B_ * H_, H_,
        D_,
        nullptr, 0, 0, 0, /*relu*/1, /*half*/1);

    // launch 3: h = fp16(relu(xp @ Wop[t,idx0]^T + bop[t,idx0]))
    gemm_f16<<<g1, blk, SMEM_BYTES>>>(
        xp_p, (size_t)B_ * H_, H_,
        Woph, (size_t)NOPS_ * H_ * H_,
        bop, (size_t)NOPS_ * H_,
        h_p, (size_t)B_ * H_, H_,
        H_,
        idx_p, 0, (size_t)H_ * H_, H_, /*relu*/1, /*half*/1);

    // launch 4: cat[:, t*H:(t+1)*H] = fp16(relu(h @ Wop[t,idx1]^T + bop[t,idx1]))
    gemm_f16<<<g1, blk, SMEM_BYTES>>>(
        h_p, (size_t)B_ * H_, H_,
        Woph, (size_t)NOPS_ * H_ * H_,
        bop, (size_t)NOPS_ * H_,
        cat_p, (size_t)H_, T_ * H_,
        H_,
        idx_p, 1, (size_t)H_ * H_, H_, /*relu*/1, /*half*/1);

    // launch 5: out = cat @ Wr^T + br   (fp32 out)  — ncu -s 5 lands here
    dim3 g4(O_ / BN, B_ / BM, 1);
    gemm_f16<<<g4, blk, SMEM_BYTES>>>(
        cat_p, 0, T_ * H_,
        Wrh, 0,
        br, 0,
        out, 0, O_,
        T_ * H_,
        nullptr, 0, 0, 0, /*relu*/0, /*half*/0);
}